// round 7
// baseline (speedup 1.0000x reference)
#include <cuda_runtime.h>
#include <cuda_bf16.h>
#include <cstdint>

#define BB 16
#define CC 256
#define HW 3136
#define CI 32
#define CG 64
#define NP 784
#define OUTC 128   /* theta(0..31) | g(32..95) | phi(96..127) */
#define EPSI 1e-5f

// ---------------- scratch ----------------
__device__ __align__(128) float d_theta[(size_t)BB*CI*HW];   // natural [b][ci][hw]
__device__ __align__(128) float d_gpool[BB*CG*NP];           // pos = r*28+c
__device__ __align__(128) float d_phipool[BB*CI*NP];
__device__ __align__(128) float d_M[BB*CI*CG];
__device__ __align__(128) float d_S[BB*1056];                // [32x32 thth^T | 32 colsum] per batch
__device__ __align__(128) __nv_bfloat16 d_Wch[OUTC*CC];      // hi  [128 o][256 k]
__device__ __align__(128) __nv_bfloat16 d_Wcl[OUTC*CC];      // lo
__device__ __align__(128) __nv_bfloat16 d_Wzh[CC*CG];        // [256 o][64 k]
__device__ __align__(128) __nv_bfloat16 d_Wzl[CC*CG];
__device__ float d_bc[OUTC];
__device__ float d_s1[CC], d_t1[CC];
__device__ float d_s2[CG], d_t2[CG];
__device__ float d_bsum[CC], d_bssq[CC];

// ---------------- helpers ----------------
#define SWZ128(off) ((off) ^ (((off) >> 3) & 0x70))
#define SWZ256(off) ((off) ^ (((off) >> 4) & 0x70))

__device__ __forceinline__ uint32_t smem_u32(const void* p) {
    uint32_t a;
    asm("{ .reg .u64 t; cvta.to.shared.u64 t, %1; cvt.u32.u64 %0, t; }" : "=r"(a) : "l"(p));
    return a;
}
__device__ __forceinline__ void ldm_x4(uint32_t* r, uint32_t addr) {
    asm volatile("ldmatrix.sync.aligned.m8n8.x4.shared.b16 {%0,%1,%2,%3}, [%4];"
        : "=r"(r[0]),"=r"(r[1]),"=r"(r[2]),"=r"(r[3]) : "r"(addr));
}
__device__ __forceinline__ void ldm_x4_t(uint32_t* r, uint32_t addr) {
    asm volatile("ldmatrix.sync.aligned.m8n8.x4.trans.shared.b16 {%0,%1,%2,%3}, [%4];"
        : "=r"(r[0]),"=r"(r[1]),"=r"(r[2]),"=r"(r[3]) : "r"(addr));
}
__device__ __forceinline__ void mma16816(float* c, const uint32_t* a, const uint32_t* b) {
    asm volatile("mma.sync.aligned.m16n8k16.row.col.f32.bf16.bf16.f32 "
        "{%0,%1,%2,%3}, {%4,%5,%6,%7}, {%8,%9}, {%0,%1,%2,%3};"
        : "+f"(c[0]),"+f"(c[1]),"+f"(c[2]),"+f"(c[3])
        : "r"(a[0]),"r"(a[1]),"r"(a[2]),"r"(a[3]), "r"(b[0]),"r"(b[1]));
}
// 128B-row SW128 frag address (A operands, k_final B)
__device__ __forceinline__ uint32_t frag_addr(uint32_t base, int row0, int colb, int lane) {
    int g = lane >> 3, i = lane & 7;
    uint32_t off = (uint32_t)((row0 + i + (g & 1) * 8) * 128 + colb + (g >> 1) * 16);
    return base + SWZ128(off);
}
// 256B-row SWZ256 frag address (k_fconv B, N=112)
__device__ __forceinline__ uint32_t frag_addr256(uint32_t base, int row0, int colb, int lane) {
    int g = lane >> 3, i = lane & 7;
    uint32_t off = (uint32_t)((row0 + i + (g & 1) * 8) * 256 + colb + (g >> 1) * 16);
    return base + SWZ256(off);
}
__device__ __forceinline__ uint32_t bf2u(__nv_bfloat162 v) {
    return *reinterpret_cast<uint32_t*>(&v);
}
// hi/lo split of fp32 pair
__device__ __forceinline__ void hl2(float f0, float f1, uint32_t& hi, uint32_t& lo) {
    __nv_bfloat162 h = __floats2bfloat162_rn(f0, f1);
    __nv_bfloat162 l = __floats2bfloat162_rn(f0 - __low2float(h), f1 - __high2float(h));
    hi = bf2u(h); lo = bf2u(l);
}

// ---------------- K0: prep ----------------
__global__ void k_prep(const float* __restrict__ wg, const float* __restrict__ wth,
                       const float* __restrict__ wphi, const float* __restrict__ wz,
                       const float* __restrict__ bg, const float* __restrict__ bth,
                       const float* __restrict__ bphi) {
    int idx = blockIdx.x * 256 + threadIdx.x;
    if (idx < OUTC * CC) {
        int o = idx >> 8, k = idx & 255;
        float w;
        if (o < 32)      w = wth[o * CC + k];
        else if (o < 96) w = wg[(o - 32) * CC + k];
        else             w = wphi[(o - 96) * CC + k];
        __nv_bfloat16 h = __float2bfloat16(w);
        d_Wch[idx] = h;
        d_Wcl[idx] = __float2bfloat16(w - __bfloat162float(h));
    }
    int j = idx - OUTC * CC;
    if (j >= 0 && j < CC * CG) {
        float w = wz[j];
        __nv_bfloat16 h = __float2bfloat16(w);
        d_Wzh[j] = h;
        d_Wzl[j] = __float2bfloat16(w - __bfloat162float(h));
    }
    int l = j - CC * CG;
    if (l >= 0 && l < OUTC)
        d_bc[l] = (l < 32) ? bth[l] : (l < 96 ? bg[l - 32] : bphi[l - 96]);
    if (l >= OUTC && l < OUTC + CC) {
        int c = l - OUTC;
        d_bsum[c] = 0.f; d_bssq[c] = 0.f;
    }
    int m = l - OUTC - CC;
    if (m >= 0 && m < BB * CI * CG) d_M[m] = 0.f;
    int s = m - BB * CI * CG;
    if (s >= 0 && s < BB * 1056) d_S[s] = 0.f;
}

// ---------------- K1: BN1 partial stats (c, batch-half) ----------------
__global__ void __launch_bounds__(256) k_bn1(const float* __restrict__ x) {
    int c = blockIdx.x;
    int bh = blockIdx.y;
    float s = 0.f, ss = 0.f;
    for (int b = bh * 8; b < bh * 8 + 8; b++) {
        const float4* p = (const float4*)(x + (size_t)(b * CC + c) * HW);
        for (int i = threadIdx.x; i < HW / 4; i += 256) {
            float4 v = p[i];
            s  += v.x + v.y + v.z + v.w;
            ss += v.x * v.x + v.y * v.y + v.z * v.z + v.w * v.w;
        }
    }
    for (int off = 16; off; off >>= 1) {
        s  += __shfl_down_sync(0xffffffffu, s, off);
        ss += __shfl_down_sync(0xffffffffu, ss, off);
    }
    __shared__ float rs[8], rss[8];
    int wid = threadIdx.x >> 5, lane = threadIdx.x & 31;
    if (lane == 0) { rs[wid] = s; rss[wid] = ss; }
    __syncthreads();
    if (threadIdx.x == 0) {
        float S = 0.f, SS = 0.f;
        for (int i = 0; i < 8; i++) { S += rs[i]; SS += rss[i]; }
        atomicAdd(&d_bsum[c], S);
        atomicAdd(&d_bssq[c], SS);
    }
}
__global__ void k_bn1fin(const float* __restrict__ g1, const float* __restrict__ b1) {
    int c = threadIdx.x;
    float n = (float)(BB * HW);
    float mean = d_bsum[c] / n;
    float var = d_bssq[c] / n - mean * mean;
    float rstd = rsqrtf(var + EPSI);
    float sc = g1[c] * rstd;
    d_s1[c] = sc;
    d_t1[c] = b1[c] - mean * sc;
}

// ---------------- K2: HMMA BN1+ReLU+conv1x1 + fused 2x2 pool ----------------
// block = 2 image rows (rowpair rp) of one batch: M=128 out, N=112 px, K=256.
// dyn smem: A_H 0..16K, A_L 16..32K (128 x 128B SW128); B_H 32..48K, B_L 48..64K (64 x 256B SWZ256)
#define F_SMEM 65536
__global__ void __launch_bounds__(256) k_fconv_mma(const float* __restrict__ x) {
    extern __shared__ __align__(128) char smem[];
    uint32_t sb = smem_u32(smem);
    const uint32_t sAH = sb, sAL = sb + 16384, sBH = sb + 32768, sBL = sb + 49152;
    int tid = threadIdx.x;
    int wid = tid >> 5, lane = tid & 31;
    int b = blockIdx.y;
    int rp = blockIdx.x;           // rowpair 0..27

    float acc[14][4];
#pragma unroll
    for (int nf = 0; nf < 14; nf++)
#pragma unroll
        for (int q = 0; q < 4; q++) acc[nf][q] = 0.f;

    for (int kc = 0; kc < 4; kc++) {
        int k0 = kc * 64;
        __syncthreads();
        // A: weights [128 o][64 k] hi/lo
#pragma unroll
        for (int r = 0; r < 4; r++) {
            int idx = tid + r * 256;
            int row = idx >> 3, j = idx & 7;
            uint32_t sw = SWZ128((uint32_t)(row * 128 + j * 16));
            *(uint4*)(smem + sw)         = *(const uint4*)(d_Wch + row * CC + k0 + j * 8);
            *(uint4*)(smem + 16384 + sw) = *(const uint4*)(d_Wcl + row * CC + k0 + j * 8);
        }
        // B: xa [64 k][112 px] hi/lo; px = y*56 + xcol
#pragma unroll
        for (int r = 0; r < 7; r++) {
            int idx = tid + r * 256;
            int ch = idx / 28, un = idx % 28;
            int y = un / 14, x4 = un % 14;
            int c = k0 + ch;
            float4 v = *(const float4*)(x + (size_t)(b * CC + c) * HW + (2 * rp + y) * 56 + x4 * 4);
            float sc = d_s1[c], sh = d_t1[c];
            float f0 = fmaxf(fmaf(v.x, sc, sh), 0.f);
            float f1 = fmaxf(fmaf(v.y, sc, sh), 0.f);
            float f2 = fmaxf(fmaf(v.z, sc, sh), 0.f);
            float f3 = fmaxf(fmaf(v.w, sc, sh), 0.f);
            uint32_t h01, l01, h23, l23;
            hl2(f0, f1, h01, l01);
            hl2(f2, f3, h23, l23);
            int px = y * 56 + x4 * 4;
            uint32_t sw = SWZ256((uint32_t)(ch * 256 + px * 2));
            *(uint2*)(smem + 32768 + sw) = make_uint2(h01, h23);
            *(uint2*)(smem + 49152 + sw) = make_uint2(l01, l23);
        }
        __syncthreads();
        // each warp owns 16 M-rows (wid*16), all 112 px
#pragma unroll
        for (int ks = 0; ks < 4; ks++) {
            int k16 = ks * 16;
            uint32_t ah[4], al[4];
            ldm_x4(ah, frag_addr(sAH, wid * 16, k16 * 2, lane));
            ldm_x4(al, frag_addr(sAL, wid * 16, k16 * 2, lane));
#pragma unroll
            for (int f = 0; f < 7; f++) {
                uint32_t bh4[4], bl4[4];
                ldm_x4_t(bh4, frag_addr256(sBH, k16, f * 32, lane));
                ldm_x4_t(bl4, frag_addr256(sBL, k16, f * 32, lane));
#pragma unroll
                for (int h = 0; h < 2; h++) {
                    mma16816(acc[2 * f + h], ah, &bh4[h * 2]);
                    mma16816(acc[2 * f + h], ah, &bl4[h * 2]);
                    mma16816(acc[2 * f + h], al, &bh4[h * 2]);
                }
            }
        }
    }
    // epilogue: warps 0-1 = theta full-res; warps 2-7 = pooled g/phi
    int g = lane >> 2, ti = lane & 3;
    if (wid < 2) {
#pragma unroll
        for (int nf = 0; nf < 14; nf++) {
            int y = nf / 7, xc = (nf % 7) * 8 + ti * 2;
            int gp = (2 * rp + y) * 56 + xc;
            int o = wid * 16 + g;
            float b0 = d_bc[o], b8 = d_bc[o + 8];
            *(float2*)(d_theta + (size_t)(b * CI + o) * HW + gp) =
                make_float2(acc[nf][0] + b0, acc[nf][1] + b0);
            *(float2*)(d_theta + (size_t)(b * CI + o + 8) * HW + gp) =
                make_float2(acc[nf][2] + b8, acc[nf][3] + b8);
        }
    } else {
        int o0 = wid * 16 + g, o8 = o0 + 8;
        float b0 = d_bc[o0], b8 = d_bc[o8];
#pragma unroll
        for (int k = 0; k < 7; k++) {
            int c = k * 4 + ti;
            int pos = rp * 28 + c;
            float v0 = fmaxf(fmaxf(acc[k][0], acc[k][1]),
                             fmaxf(acc[k + 7][0], acc[k + 7][1])) + b0;
            float v8 = fmaxf(fmaxf(acc[k][2], acc[k][3]),
                             fmaxf(acc[k + 7][2], acc[k + 7][3])) + b8;
            int c0 = o0 - 32, c8 = o8 - 32;
            if (c0 < 64) d_gpool[(b * CG + c0) * NP + pos] = v0;
            else         d_phipool[(b * CI + (c0 - 64)) * NP + pos] = v0;
            if (c8 < 64) d_gpool[(b * CG + c8) * NP + pos] = v8;
            else         d_phipool[(b * CI + (c8 - 64)) * NP + pos] = v8;
        }
    }
}

// ---------------- K3: S = theta theta^T + colsum (per batch, 4 px-chunks) ----------------
__global__ void __launch_bounds__(256) k_S() {
    int b = blockIdx.y, chunk = blockIdx.x;   // chunk of 784 px
    __shared__ float Th[32][57];
    int tid = threadIdx.x;
    int i = tid >> 3, j0 = (tid & 7) * 4;
    float a0 = 0.f, a1 = 0.f, a2 = 0.f, a3 = 0.f;
    float cs = 0.f;
    int base = chunk * 784;
    for (int t = 0; t < 14; t++) {
        __syncthreads();
        for (int u = tid; u < 448; u += 256) {
            int r = u / 14, q = u % 14;
            float4 v = *(const float4*)(d_theta + (size_t)(b * CI + r) * HW + base + t * 56 + q * 4);
            Th[r][q * 4] = v.x; Th[r][q * 4 + 1] = v.y;
            Th[r][q * 4 + 2] = v.z; Th[r][q * 4 + 3] = v.w;
        }
        __syncthreads();
#pragma unroll 8
        for (int p = 0; p < 56; p++) {
            float tv = Th[i][p];
            a0 = fmaf(tv, Th[j0][p], a0);
            a1 = fmaf(tv, Th[j0 + 1][p], a1);
            a2 = fmaf(tv, Th[j0 + 2][p], a2);
            a3 = fmaf(tv, Th[j0 + 3][p], a3);
        }
        if (tid < 32) {
#pragma unroll 8
            for (int p = 0; p < 56; p++) cs += Th[tid][p];
        }
    }
    float* Sb = d_S + b * 1056;
    atomicAdd(&Sb[i * 32 + j0], a0);
    atomicAdd(&Sb[i * 32 + j0 + 1], a1);
    atomicAdd(&Sb[i * 32 + j0 + 2], a2);
    atomicAdd(&Sb[i * 32 + j0 + 3], a3);
    if (tid < 32) atomicAdd(&Sb[1024 + tid], cs);
}

// ---------------- K4: M[b] = phi_pool @ g_pool^T ----------------
__global__ void __launch_bounds__(512) k_M() {
    int b = blockIdx.y;
    int m0 = blockIdx.x * 112;
    __shared__ float Ps[CI][113];
    __shared__ float Gs[CG][113];
    int tid = threadIdx.x;
    for (int j = tid; j < CI * 112; j += 512) {
        int i = j / 112, mm = j % 112;
        Ps[i][mm] = d_phipool[(b * CI + i) * NP + m0 + mm];
    }
    for (int j = tid; j < CG * 112; j += 512) {
        int i = j / 112, mm = j % 112;
        Gs[i][mm] = d_gpool[(b * CG + i) * NP + m0 + mm];
    }
    __syncthreads();
#pragma unroll
    for (int q = 0; q < 4; q++) {
        int o = tid + q * 512;
        int i = o >> 6, c = o & 63;
        float acc = 0.f;
#pragma unroll 8
        for (int mm = 0; mm < 112; mm++) acc = fmaf(Ps[i][mm], Gs[c][mm], acc);
        atomicAdd(&d_M[(b * CI + i) * CG + c], acc);
    }
}

// ---------------- K5: BN2 scale/shift from analytic moments ----------------
__global__ void __launch_bounds__(1024) k_bn2a(const float* __restrict__ g2,
                                               const float* __restrict__ b2) {
    __shared__ float ssum[64][17], ssq[64][17];
    int t = threadIdx.x;
    int b = t >> 6, c = t & 63;
    const float invNp = 1.0f / (float)NP;
    float v[32];
#pragma unroll
    for (int i = 0; i < 32; i++) v[i] = d_M[(b * CI + i) * CG + c] * invNp;
    const float* Sb = d_S + b * 1056;
    float sm = 0.f, sq = 0.f;
#pragma unroll 4
    for (int i = 0; i < 32; i++) {
        float row = 0.f;
#pragma unroll 8
        for (int j = 0; j < 32; j++) row = fmaf(Sb[i * 32 + j], v[j], row);
        sq = fmaf(v[i], row, sq);
        sm = fmaf(v[i], Sb[1024 + i], sm);
    }
    ssum[c][b] = sm;
    ssq[c][b] = sq;
    __syncthreads();
    if (t < 64) {
        float S = 0.f, Q = 0.f;
        for (int bb = 0; bb < 16; bb++) { S += ssum[t][bb]; Q += ssq[t][bb]; }
        float n = (float)(BB * HW);
        float mean = S / n;
        float var = Q / n - mean * mean;
        float rstd = rsqrtf(var + EPSI);
        float sc = g2[t] * rstd;
        d_s2[t] = sc;
        d_t2[t] = b2[t] - mean * sc;
    }
}

// ---------------- K6: fused y-recompute + BN2 + ReLU + conv(64->256) + identity ----------------
// dyn smem: A_H 0..32K, A_L 32..64K, B_H 64..72K, B_L 72..80K, Th 80..88K, Ms 88..96K
#define Z_SMEM 98304
__global__ void __launch_bounds__(256) k_final_mma(const float* __restrict__ x,
                                                   const float* __restrict__ bz,
                                                   float* __restrict__ out) {
    extern __shared__ __align__(128) char smem[];
    uint32_t sb = smem_u32(smem);
    const uint32_t sAH = sb, sAL = sb + 32768, sBH = sb + 65536, sBL = sb + 73728;
    float* Th = (float*)(smem + 81920);
    float* Ms = (float*)(smem + 90112);
    int tid = threadIdx.x;
    int wid = tid >> 5, lane = tid & 31;
    int wm = wid >> 1, wn = wid & 1;
    int b = blockIdx.y;
    int p0 = blockIdx.x * 64;
    const float invNp = 1.0f / (float)NP;

    // A: w_z [256 o][64 k] hi/lo
#pragma unroll
    for (int r = 0; r < 8; r++) {
        int idx = tid + r * 256;
        int row = idx >> 3, j = idx & 7;
        uint32_t sw = SWZ128((uint32_t)(row * 128 + j * 16));
        *(uint4*)(smem + sw)         = *(const uint4*)(d_Wzh + row * CG + j * 8);
        *(uint4*)(smem + 32768 + sw) = *(const uint4*)(d_Wzl + row * CG + j * 8);
    }
    // theta tile [32][64] + M/Np [32][64] to smem
#pragma unroll
    for (int r = 0; r < 2; r++) {
        int idx = tid + r * 256;
        int i = idx >> 4, q = idx & 15;
        *(float4*)(Th + i * 64 + q * 4) =
            *(const float4*)(d_theta + (size_t)(b * CI + i) * HW + p0 + q * 4);
    }
#pragma unroll
    for (int r = 0; r < 2; r++) {
        int idx = tid + r * 256;
        float4 v = *(const float4*)(d_M + b * CI * CG + idx * 4);
        v.x *= invNp; v.y *= invNp; v.z *= invNp; v.w *= invNp;
        *(float4*)(Ms + idx * 4) = v;
    }
    __syncthreads();

    // y tile [64 cg][64 px] = M^T theta; BN2+ReLU; hi/lo -> B operand
    {
        int cg = tid & 63, pg = tid >> 6;
        float yv[16];
#pragma unroll
        for (int q = 0; q < 16; q++) yv[q] = 0.f;
#pragma unroll 8
        for (int i = 0; i < 32; i++) {
            float m = Ms[i * 64 + cg];
            const float* tr = Th + i * 64 + pg * 16;
#pragma unroll
            for (int q = 0; q < 16; q++) yv[q] = fmaf(m, tr[q], yv[q]);
        }
        float sc = d_s2[cg], sh = d_t2[cg];
#pragma unroll
        for (int q = 0; q < 16; q++) yv[q] = fmaxf(fmaf(yv[q], sc, sh), 0.f);
#pragma unroll
        for (int q = 0; q < 16; q += 4) {
            uint32_t h01, l01, h23, l23;
            hl2(yv[q], yv[q + 1], h01, l01);
            hl2(yv[q + 2], yv[q + 3], h23, l23);
            int px = pg * 16 + q;
            uint32_t sw = SWZ128((uint32_t)(cg * 128 + px * 2));
            *(uint2*)(smem + 65536 + sw) = make_uint2(h01, h23);
            *(uint2*)(smem + 73728 + sw) = make_uint2(l01, l23);
        }
    }
    __syncthreads();

    float acc[4][4][4];
#pragma unroll
    for (int mt = 0; mt < 4; mt++)
#pragma unroll
        for (int nf = 0; nf < 4; nf++)
#pragma unroll
            for (int q = 0; q < 4; q++) acc[mt][nf][q] = 0.f;

#pragma unroll
    for (int ks = 0; ks < 4; ks++) {
        int k16 = ks * 16;
        uint32_t bh[2][4], bl[2][4];
        ldm_x4_t(bh[0], frag_addr(sBH, k16, wn * 64, lane));
        ldm_x4_t(bh[1], frag_addr(sBH, k16, wn * 64 + 32, lane));
        ldm_x4_t(bl[0], frag_addr(sBL, k16, wn * 64, lane));
        ldm_x4_t(bl[1], frag_addr(sBL, k16, wn * 64 + 32, lane));
#pragma unroll
        for (int mt = 0; mt < 4; mt++) {
            uint32_t ah[4], al[4];
            ldm_x4(ah, frag_addr(sAH, wm * 64 + mt * 16, k16 * 2, lane));
            ldm_x4(al, frag_addr(sAL, wm * 64 + mt * 16, k16 * 2, lane));
#pragma unroll
            for (int nf = 0; nf < 4; nf++) {
                const uint32_t* bhf = &bh[nf >> 1][(nf & 1) * 2];
                const uint32_t* blf = &bl[nf >> 1][(nf & 1) * 2];
                mma16816(acc[mt][nf], ah, bhf);
                mma16816(acc[mt][nf], ah, blf);
                mma16816(acc[mt][nf], al, bhf);
            }
        }
    }
    // epilogue: + bias + identity
    int g = lane >> 2, ti = lane & 3;
#pragma unroll
    for (int mt = 0; mt < 4; mt++) {
#pragma unroll
        for (int nf = 0; nf < 4; nf++) {
            int o = wm * 64 + mt * 16 + g;
            int pix = p0 + wn * 32 + nf * 8 + ti * 2;
            float b0 = __ldg(&bz[o]), b8 = __ldg(&bz[o + 8]);
            size_t off0 = (size_t)(b * CC + o) * HW + pix;
            size_t off1 = (size_t)(b * CC + o + 8) * HW + pix;
            float2 i0 = *(const float2*)(x + off0);
            float2 i1 = *(const float2*)(x + off1);
            *(float2*)(out + off0) = make_float2(acc[mt][nf][0] + b0 + i0.x,
                                                 acc[mt][nf][1] + b0 + i0.y);
            *(float2*)(out + off1) = make_float2(acc[mt][nf][2] + b8 + i1.x,
                                                 acc[mt][nf][3] + b8 + i1.y);
        }
    }
}

// ---------------- host ----------------
extern "C" void kernel_launch(void* const* d_in, const int* in_sizes, int n_in,
                              void* d_out, int out_size) {
    const float* x   = (const float*)d_in[0];
    const float* g1  = (const float*)d_in[1];
    const float* b1  = (const float*)d_in[2];
    const float* wg  = (const float*)d_in[3];
    const float* bg  = (const float*)d_in[4];
    const float* wth = (const float*)d_in[5];
    const float* bth = (const float*)d_in[6];
    const float* wph = (const float*)d_in[7];
    const float* bph = (const float*)d_in[8];
    const float* g2  = (const float*)d_in[9];
    const float* b2  = (const float*)d_in[10];
    const float* wz  = (const float*)d_in[11];
    const float* bz  = (const float*)d_in[12];
    float* out = (float*)d_out;

    static bool attr_set = false;
    if (!attr_set) {
        cudaFuncSetAttribute(k_fconv_mma, cudaFuncAttributeMaxDynamicSharedMemorySize, F_SMEM);
        cudaFuncSetAttribute(k_final_mma, cudaFuncAttributeMaxDynamicSharedMemorySize, Z_SMEM);
        attr_set = true;
    }

    int prep_elems = OUTC * CC + CC * CG + OUTC + CC + BB * CI * CG + BB * 1056;
    k_prep<<<(prep_elems + 255) / 256, 256>>>(wg, wth, wph, wz, bg, bth, bph);
    {
        dim3 g(CC, 2);
        k_bn1<<<g, 256>>>(x);
    }
    k_bn1fin<<<1, CC>>>(g1, b1);
    {
        dim3 g(28, BB);
        k_fconv_mma<<<g, 256, F_SMEM>>>(x);
    }
    {
        dim3 g(4, BB);
        k_S<<<g, 256>>>();
    }
    {
        dim3 g(7, BB);
        k_M<<<g, 512>>>();
    }
    k_bn2a<<<1, 1024>>>(g2, b2);
    {
        dim3 g(49, BB);
        k_final_mma<<<g, 256, Z_SMEM>>>(x, bz, out);
    }
}

// round 8
// speedup vs baseline: 1.5843x; 1.5843x over previous
#include <cuda_runtime.h>
#include <cuda_bf16.h>
#include <cstdint>

#define BB 16
#define CC 256
#define HW 3136
#define CI 32
#define CG 64
#define NP 784
#define OUTC 128   /* theta(0..31) | g(32..95) | phi(96..127) */
#define EPSI 1e-5f
#define KAR_INV 0.03125f

// ---------------- scratch ----------------
__device__ __align__(128) float d_conv[(size_t)BB*OUTC*HW];
__device__ __align__(128) float d_M[BB*CI*CG];
__device__ __align__(128) __nv_bfloat16 d_yh[(size_t)BB*CG*HW];
__device__ __align__(128) __nv_bfloat16 d_yl[(size_t)BB*CG*HW];
__device__ __align__(128) __nv_bfloat16 d_Wch[OUTC*CC];   // hi  [128 o][256 k]
__device__ __align__(128) __nv_bfloat16 d_Wc2[OUTC*CC];   // karatsuba bf16(32w-31hi)
__device__ __align__(128) __nv_bfloat16 d_Wzh[CC*CG];     // [256 o][64 k] hi
__device__ __align__(128) __nv_bfloat16 d_Wzl[CC*CG];     // lo
__device__ float d_bc[OUTC];
__device__ float d_s1[CC], d_t1[CC];
__device__ float d_s2[CG], d_t2[CG];
__device__ float d_ysum[CG], d_ysumsq[CG];

// ---------------- helpers ----------------
#define SWZ128(off) ((off) ^ (((off) >> 3) & 0x70))

__device__ __forceinline__ uint32_t smem_u32(const void* p) {
    uint32_t a;
    asm("{ .reg .u64 t; cvta.to.shared.u64 t, %1; cvt.u32.u64 %0, t; }" : "=r"(a) : "l"(p));
    return a;
}
__device__ __forceinline__ void ldm_x4(uint32_t* r, uint32_t addr) {
    asm volatile("ldmatrix.sync.aligned.m8n8.x4.shared.b16 {%0,%1,%2,%3}, [%4];"
        : "=r"(r[0]),"=r"(r[1]),"=r"(r[2]),"=r"(r[3]) : "r"(addr));
}
__device__ __forceinline__ void ldm_x4_t(uint32_t* r, uint32_t addr) {
    asm volatile("ldmatrix.sync.aligned.m8n8.x4.trans.shared.b16 {%0,%1,%2,%3}, [%4];"
        : "=r"(r[0]),"=r"(r[1]),"=r"(r[2]),"=r"(r[3]) : "r"(addr));
}
__device__ __forceinline__ void mma16816(float* c, const uint32_t* a, const uint32_t* b) {
    asm volatile("mma.sync.aligned.m16n8k16.row.col.f32.bf16.bf16.f32 "
        "{%0,%1,%2,%3}, {%4,%5,%6,%7}, {%8,%9}, {%0,%1,%2,%3};"
        : "+f"(c[0]),"+f"(c[1]),"+f"(c[2]),"+f"(c[3])
        : "r"(a[0]),"r"(a[1]),"r"(a[2]),"r"(a[3]), "r"(b[0]),"r"(b[1]));
}
__device__ __forceinline__ uint32_t frag_addr(uint32_t base, int row0, int colb, int lane) {
    int g = lane >> 3, i = lane & 7;
    uint32_t off = (uint32_t)((row0 + i + (g & 1) * 8) * 128 + colb + (g >> 1) * 16);
    return base + SWZ128(off);
}
__device__ __forceinline__ uint32_t bf2u(__nv_bfloat162 v) {
    return *reinterpret_cast<uint32_t*>(&v);
}
__device__ __forceinline__ float2 u2f2(uint32_t u) {
    __nv_bfloat162 v = *reinterpret_cast<__nv_bfloat162*>(&u);
    return make_float2(__low2float(v), __high2float(v));
}
// karatsuba split: hi bf16, then bf16(32f - 31hi)
__device__ __forceinline__ void kar2(float f0, float f1, uint32_t& hi, uint32_t& k2) {
    __nv_bfloat162 h = __floats2bfloat162_rn(f0, f1);
    float h0 = __low2float(h), h1 = __high2float(h);
    __nv_bfloat162 s = __floats2bfloat162_rn(fmaf(32.f, f0, -31.f * h0),
                                             fmaf(32.f, f1, -31.f * h1));
    hi = bf2u(h); k2 = bf2u(s);
}
__device__ __forceinline__ float karc(float d1, float d2) { return fmaf(d2 - d1, KAR_INV, d1); }
// plain hi/lo split
__device__ __forceinline__ void hl2(float f0, float f1, uint32_t& hi, uint32_t& lo) {
    __nv_bfloat162 h = __floats2bfloat162_rn(f0, f1);
    __nv_bfloat162 l = __floats2bfloat162_rn(f0 - __low2float(h), f1 - __high2float(h));
    hi = bf2u(h); lo = bf2u(l);
}
// packed f32x2
__device__ __forceinline__ unsigned long long pk2(float lo, float hi) {
    unsigned long long r;
    asm("mov.b64 %0, {%1, %2};" : "=l"(r) : "f"(lo), "f"(hi));
    return r;
}
__device__ __forceinline__ void fma2(unsigned long long& d, unsigned long long a, unsigned long long b) {
    asm("fma.rn.f32x2 %0, %1, %2, %0;" : "+l"(d) : "l"(a), "l"(b));
}
__device__ __forceinline__ float2 upk2(unsigned long long v) {
    float lo, hi;
    asm("mov.b64 {%0, %1}, %2;" : "=f"(lo), "=f"(hi) : "l"(v));
    return make_float2(lo, hi);
}

// ---------------- K0: prep ----------------
__global__ void k_prep(const float* __restrict__ wg, const float* __restrict__ wth,
                       const float* __restrict__ wphi, const float* __restrict__ wz,
                       const float* __restrict__ bg, const float* __restrict__ bth,
                       const float* __restrict__ bphi) {
    int idx = blockIdx.x * 256 + threadIdx.x;
    if (idx < OUTC * CC) {
        int o = idx >> 8, k = idx & 255;
        float w;
        if (o < 32)      w = wth[o * CC + k];
        else if (o < 96) w = wg[(o - 32) * CC + k];
        else             w = wphi[(o - 96) * CC + k];
        __nv_bfloat16 h = __float2bfloat16(w);
        d_Wch[idx] = h;
        d_Wc2[idx] = __float2bfloat16(fmaf(32.f, w, -31.f * __bfloat162float(h)));
    }
    int j = idx - OUTC * CC;
    if (j >= 0 && j < CC * CG) {
        float w = wz[j];
        __nv_bfloat16 h = __float2bfloat16(w);
        d_Wzh[j] = h;
        d_Wzl[j] = __float2bfloat16(w - __bfloat162float(h));
    }
    int l = j - CC * CG;
    if (l >= 0 && l < OUTC)
        d_bc[l] = (l < 32) ? bth[l] : (l < 96 ? bg[l - 32] : bphi[l - 96]);
    if (l >= OUTC && l < OUTC + CG) {
        int c = l - OUTC;
        d_ysum[c] = 0.f; d_ysumsq[c] = 0.f;
    }
    int m = l - OUTC - CG;
    if (m >= 0 && m < BB * CI * CG) d_M[m] = 0.f;
}

// ---------------- K1: BN1 stats ----------------
__global__ void __launch_bounds__(256) k_bn1(const float* __restrict__ x,
                                             const float* __restrict__ g1,
                                             const float* __restrict__ b1) {
    int c = blockIdx.x;
    float s = 0.f, ss = 0.f;
    for (int b = 0; b < BB; b++) {
        const float4* p = (const float4*)(x + (size_t)(b * CC + c) * HW);
        for (int i = threadIdx.x; i < HW / 4; i += 256) {
            float4 v = p[i];
            s  += v.x + v.y + v.z + v.w;
            ss += v.x * v.x + v.y * v.y + v.z * v.z + v.w * v.w;
        }
    }
    for (int off = 16; off; off >>= 1) {
        s  += __shfl_down_sync(0xffffffffu, s, off);
        ss += __shfl_down_sync(0xffffffffu, ss, off);
    }
    __shared__ float rs[8], rss[8];
    int wid = threadIdx.x >> 5, lane = threadIdx.x & 31;
    if (lane == 0) { rs[wid] = s; rss[wid] = ss; }
    __syncthreads();
    if (threadIdx.x == 0) {
        float S = 0.f, SS = 0.f;
        for (int i = 0; i < 8; i++) { S += rs[i]; SS += rss[i]; }
        float n = (float)(BB * HW);
        float mean = S / n;
        float var = SS / n - mean * mean;
        float rstd = rsqrtf(var + EPSI);
        float sc = g1[c] * rstd;
        d_s1[c] = sc;
        d_t1[c] = b1[c] - mean * sc;
    }
}

// ---------------- K2: HMMA fused BN1+ReLU+conv1x1 (M=128, N=64, K=256), karatsuba 2-pass ----------------
__global__ void __launch_bounds__(256) k_fconv_mma(const float* __restrict__ x) {
    __shared__ __align__(128) char smem[49152];
    uint32_t sb = smem_u32(smem);
    const uint32_t sAH = sb, sA2 = sb + 16384, sBH = sb + 32768, sB2 = sb + 40960;
    int tid = threadIdx.x;
    int wid = tid >> 5, lane = tid & 31;
    int wm = wid >> 1, wn = wid & 1;
    int b = blockIdx.y;
    int p0 = blockIdx.x * 64;

    float a1[2][4][4], a2c[2][4][4];
#pragma unroll
    for (int mt = 0; mt < 2; mt++)
#pragma unroll
        for (int nf = 0; nf < 4; nf++)
#pragma unroll
            for (int q = 0; q < 4; q++) { a1[mt][nf][q] = 0.f; a2c[mt][nf][q] = 0.f; }

    for (int kc = 0; kc < 4; kc++) {
        int k0 = kc * 64;
        __syncthreads();
#pragma unroll
        for (int r = 0; r < 4; r++) {
            int idx = tid + r * 256;
            int row = idx >> 3, j = idx & 7;
            uint32_t sw = SWZ128((uint32_t)(row * 128 + j * 16));
            *(uint4*)(smem + sw)         = *(const uint4*)(d_Wch + row * CC + k0 + j * 8);
            *(uint4*)(smem + 16384 + sw) = *(const uint4*)(d_Wc2 + row * CC + k0 + j * 8);
        }
#pragma unroll
        for (int r = 0; r < 4; r++) {
            int idx = tid + r * 256;
            int ch = idx >> 4, pg = idx & 15;
            int c = k0 + ch;
            float4 v = *(const float4*)(x + (size_t)(b * CC + c) * HW + p0 + pg * 4);
            float sc = d_s1[c], sh = d_t1[c];
            float f0 = fmaxf(fmaf(v.x, sc, sh), 0.f);
            float f1 = fmaxf(fmaf(v.y, sc, sh), 0.f);
            float f2 = fmaxf(fmaf(v.z, sc, sh), 0.f);
            float f3 = fmaxf(fmaf(v.w, sc, sh), 0.f);
            uint32_t h01, k01, h23, k23;
            kar2(f0, f1, h01, k01);
            kar2(f2, f3, h23, k23);
            uint32_t sw = SWZ128((uint32_t)(ch * 128 + pg * 8));
            *(uint2*)(smem + 32768 + sw) = make_uint2(h01, h23);
            *(uint2*)(smem + 40960 + sw) = make_uint2(k01, k23);
        }
        __syncthreads();
#pragma unroll
        for (int ks = 0; ks < 4; ks++) {
            int k16 = ks * 16;
            uint32_t bh[2][4], b2[2][4];
            ldm_x4_t(bh[0], frag_addr(sBH, k16, wn * 64, lane));
            ldm_x4_t(bh[1], frag_addr(sBH, k16, wn * 64 + 32, lane));
            ldm_x4_t(b2[0], frag_addr(sB2, k16, wn * 64, lane));
            ldm_x4_t(b2[1], frag_addr(sB2, k16, wn * 64 + 32, lane));
#pragma unroll
            for (int mt = 0; mt < 2; mt++) {
                uint32_t ah[4], ak[4];
                ldm_x4(ah, frag_addr(sAH, wm * 32 + mt * 16, k16 * 2, lane));
                ldm_x4(ak, frag_addr(sA2, wm * 32 + mt * 16, k16 * 2, lane));
#pragma unroll
                for (int nf = 0; nf < 4; nf++) {
                    mma16816(a1[mt][nf], ah, &bh[nf >> 1][(nf & 1) * 2]);
                    mma16816(a2c[mt][nf], ak, &b2[nf >> 1][(nf & 1) * 2]);
                }
            }
        }
    }
    int g = lane >> 2, ti = lane & 3;
#pragma unroll
    for (int mt = 0; mt < 2; mt++) {
#pragma unroll
        for (int nf = 0; nf < 4; nf++) {
            int o = wm * 32 + mt * 16 + g;
            int pix = p0 + wn * 32 + nf * 8 + ti * 2;
            float b0 = d_bc[o], b8 = d_bc[o + 8];
            float* d0 = d_conv + (size_t)(b * OUTC + o) * HW + pix;
            float* d1 = d_conv + (size_t)(b * OUTC + o + 8) * HW + pix;
            *(float2*)d0 = make_float2(karc(a1[mt][nf][0], a2c[mt][nf][0]) + b0,
                                       karc(a1[mt][nf][1], a2c[mt][nf][1]) + b0);
            *(float2*)d1 = make_float2(karc(a1[mt][nf][2], a2c[mt][nf][2]) + b8,
                                       karc(a1[mt][nf][3], a2c[mt][nf][3]) + b8);
        }
    }
}

// ---------------- K4: fused 2x2 pool + M[b] = phi_pool @ g_pool^T ----------------
__global__ void __launch_bounds__(512) k_M() {
    int b = blockIdx.y;
    int pr0 = blockIdx.x * 4;          // pooled row base (4 pooled rows = 112 positions)
    __shared__ float Ps[CI][113];
    __shared__ float Gs[CG][113];
    int tid = threadIdx.x;
    // pooling loads: 96 channels x 4 pooled rows x 14 float4-quads
    for (int u = tid; u < 96 * 56; u += 512) {
        int ch = u / 56, rem = u % 56;
        int prow = rem / 14, q4 = rem % 14;
        int crow = (pr0 + prow) * 2;
        const float* src = d_conv + (size_t)(b * OUTC + 32 + ch) * HW + crow * 56 + q4 * 4;
        float4 r0 = *(const float4*)src;
        float4 r1 = *(const float4*)(src + 56);
        float o0 = fmaxf(fmaxf(r0.x, r0.y), fmaxf(r1.x, r1.y));
        float o1 = fmaxf(fmaxf(r0.z, r0.w), fmaxf(r1.z, r1.w));
        int pp = prow * 28 + q4 * 2;
        if (ch < 64) { Gs[ch][pp] = o0; Gs[ch][pp + 1] = o1; }
        else         { Ps[ch - 64][pp] = o0; Ps[ch - 64][pp + 1] = o1; }
    }
    __syncthreads();
#pragma unroll
    for (int q = 0; q < 4; q++) {
        int o = tid + q * 512;
        int i = o >> 6, c = o & 63;
        float acc = 0.f;
#pragma unroll 8
        for (int mm = 0; mm < 112; mm++) acc = fmaf(Ps[i][mm], Gs[c][mm], acc);
        atomicAdd(&d_M[(b * CI + i) * CG + c], acc);
    }
}

// ---------------- K5: y = (M/Np)^T @ theta + BN2 stats; y stored bf16 hi/lo ----------------
__global__ void __launch_bounds__(256) k_Y() {
    int b = blockIdx.y;
    int p0 = blockIdx.x * 64;
    __shared__ float Ms[CI * CG];
    __shared__ float Ts[CI * 64];
    __shared__ float bs[CG], bss[CG];
    int tid = threadIdx.x;
    const float invNp = 1.0f / (float)NP;
    for (int j = tid; j < CI * CG; j += 256) Ms[j] = d_M[b * CI * CG + j] * invNp;
    for (int j = tid; j < CI * 64; j += 256) {
        int i = j >> 6, col = j & 63;
        Ts[j] = d_conv[(size_t)(b * OUTC + i) * HW + p0 + col];
    }
    if (tid < CG) { bs[tid] = 0.f; bss[tid] = 0.f; }
    __syncthreads();
    int tx = tid & 15, ty = tid >> 4;
    unsigned long long acc[4][2];
#pragma unroll
    for (int ci = 0; ci < 4; ci++) { acc[ci][0] = 0ull; acc[ci][1] = 0ull; }
#pragma unroll 8
    for (int i = 0; i < CI; i++) {
        float4 mv = *(float4*)&Ms[i * CG + ty * 4];
        float4 tv = *(float4*)&Ts[i * 64 + tx * 4];
        unsigned long long t01 = pk2(tv.x, tv.y), t23 = pk2(tv.z, tv.w);
        float mm[4] = {mv.x, mv.y, mv.z, mv.w};
#pragma unroll
        for (int ci = 0; ci < 4; ci++) {
            unsigned long long md = pk2(mm[ci], mm[ci]);
            fma2(acc[ci][0], md, t01);
            fma2(acc[ci][1], md, t23);
        }
    }
#pragma unroll
    for (int ci = 0; ci < 4; ci++) {
        int cg = ty * 4 + ci;
        float2 a = upk2(acc[ci][0]), c2 = upk2(acc[ci][1]);
        uint32_t h01, l01, h23, l23;
        hl2(a.x, a.y, h01, l01);
        hl2(c2.x, c2.y, h23, l23);
        size_t yi = (size_t)(b * CG + cg) * HW + p0 + tx * 4;
        *(uint2*)(d_yh + yi) = make_uint2(h01, h23);
        *(uint2*)(d_yl + yi) = make_uint2(l01, l23);
        atomicAdd(&bs[cg], a.x + a.y + c2.x + c2.y);
        atomicAdd(&bss[cg], a.x * a.x + a.y * a.y + c2.x * c2.x + c2.y * c2.y);
    }
    __syncthreads();
    if (tid < CG) {
        atomicAdd(&d_ysum[tid], bs[tid]);
        atomicAdd(&d_ysumsq[tid], bss[tid]);
    }
}

// ---------------- K5b: BN2 scale/shift ----------------
__global__ void k_bn2(const float* __restrict__ g2, const float* __restrict__ b2) {
    int c = threadIdx.x;
    if (c < CG) {
        float n = (float)(BB * HW);
        float mean = d_ysum[c] / n;
        float var = d_ysumsq[c] / n - mean * mean;
        float rstd = rsqrtf(var + EPSI);
        float sc = g2[c] * rstd;
        d_s2[c] = sc;
        d_t2[c] = b2[c] - mean * sc;
    }
}

// ---------------- K6: HMMA BN2+ReLU+conv(64->256)+bias+identity (3-pass) ----------------
// dyn smem: A_H 0..32K, A_L 32..64K, B_H 64..72K, B_L 72..80K
#define Z_SMEM 81920
__global__ void __launch_bounds__(256) k_final_mma(const float* __restrict__ x,
                                                   const float* __restrict__ bz,
                                                   float* __restrict__ out) {
    extern __shared__ __align__(128) char smem[];
    uint32_t sb = smem_u32(smem);
    const uint32_t sAH = sb, sAL = sb + 32768, sBH = sb + 65536, sBL = sb + 73728;
    int tid = threadIdx.x;
    int wid = tid >> 5, lane = tid & 31;
    int wm = wid >> 1, wn = wid & 1;
    int b = blockIdx.y;
    int p0 = blockIdx.x * 64;

#pragma unroll
    for (int r = 0; r < 8; r++) {
        int idx = tid + r * 256;
        int row = idx >> 3, j = idx & 7;
        uint32_t sw = SWZ128((uint32_t)(row * 128 + j * 16));
        *(uint4*)(smem + sw)         = *(const uint4*)(d_Wzh + row * CG + j * 8);
        *(uint4*)(smem + 32768 + sw) = *(const uint4*)(d_Wzl + row * CG + j * 8);
    }
#pragma unroll
    for (int r = 0; r < 4; r++) {
        int idx = tid + r * 256;
        int ch = idx >> 4, pg = idx & 15;
        size_t yi = (size_t)(b * CG + ch) * HW + p0 + pg * 4;
        uint2 hv = *(const uint2*)(d_yh + yi);
        uint2 lv = *(const uint2*)(d_yl + yi);
        float2 h0 = u2f2(hv.x), h1 = u2f2(hv.y);
        float2 l0 = u2f2(lv.x), l1 = u2f2(lv.y);
        float sc = d_s2[ch], sh = d_t2[ch];
        float f0 = fmaxf(fmaf(h0.x + l0.x, sc, sh), 0.f);
        float f1 = fmaxf(fmaf(h0.y + l0.y, sc, sh), 0.f);
        float f2 = fmaxf(fmaf(h1.x + l1.x, sc, sh), 0.f);
        float f3 = fmaxf(fmaf(h1.y + l1.y, sc, sh), 0.f);
        uint32_t h01, l01, h23, l23;
        hl2(f0, f1, h01, l01);
        hl2(f2, f3, h23, l23);
        uint32_t sw = SWZ128((uint32_t)(ch * 128 + pg * 8));
        *(uint2*)(smem + 65536 + sw) = make_uint2(h01, h23);
        *(uint2*)(smem + 73728 + sw) = make_uint2(l01, l23);
    }
    __syncthreads();

    float acc[4][4][4];
#pragma unroll
    for (int mt = 0; mt < 4; mt++)
#pragma unroll
        for (int nf = 0; nf < 4; nf++)
#pragma unroll
            for (int q = 0; q < 4; q++) acc[mt][nf][q] = 0.f;

#pragma unroll
    for (int ks = 0; ks < 4; ks++) {
        int k16 = ks * 16;
        uint32_t bh[2][4], bl[2][4];
        ldm_x4_t(bh[0], frag_addr(sBH, k16, wn * 64, lane));
        ldm_x4_t(bh[1], frag_addr(sBH, k16, wn * 64 + 32, lane));
        ldm_x4_t(bl[0], frag_addr(sBL, k16, wn * 64, lane));
        ldm_x4_t(bl[1], frag_addr(sBL, k16, wn * 64 + 32, lane));
#pragma unroll
        for (int mt = 0; mt < 4; mt++) {
            uint32_t ah[4], al[4];
            ldm_x4(ah, frag_addr(sAH, wm * 64 + mt * 16, k16 * 2, lane));
            ldm_x4(al, frag_addr(sAL, wm * 64 + mt * 16, k16 * 2, lane));
#pragma unroll
            for (int nf = 0; nf < 4; nf++) {
                const uint32_t* bhf = &bh[nf >> 1][(nf & 1) * 2];
                const uint32_t* blf = &bl[nf >> 1][(nf & 1) * 2];
                mma16816(acc[mt][nf], ah, bhf);
                mma16816(acc[mt][nf], ah, blf);
                mma16816(acc[mt][nf], al, bhf);
            }
        }
    }
    int g = lane >> 2, ti = lane & 3;
#pragma unroll
    for (int mt = 0; mt < 4; mt++) {
#pragma unroll
        for (int nf = 0; nf < 4; nf++) {
            int o = wm * 64 + mt * 16 + g;
            int pix = p0 + wn * 32 + nf * 8 + ti * 2;
            float b0 = __ldg(&bz[o]), b8 = __ldg(&bz[o + 8]);
            size_t off0 = (size_t)(b * CC + o) * HW + pix;
            size_t off1 = (size_t)(b * CC + o + 8) * HW + pix;
            float2 i0 = *(const float2*)(x + off0);
            float2 i1 = *(const float2*)(x + off1);
            *(float2*)(out + off0) = make_float2(acc[mt][nf][0] + b0 + i0.x,
                                                 acc[mt][nf][1] + b0 + i0.y);
            *(float2*)(out + off1) = make_float2(acc[mt][nf][2] + b8 + i1.x,
                                                 acc[mt][nf][3] + b8 + i1.y);
        }
    }
}

// ---------------- host ----------------
extern "C" void kernel_launch(void* const* d_in, const int* in_sizes, int n_in,
                              void* d_out, int out_size) {
    const float* x   = (const float*)d_in[0];
    const float* g1  = (const float*)d_in[1];
    const float* b1  = (const float*)d_in[2];
    const float* wg  = (const float*)d_in[3];
    const float* bg  = (const float*)d_in[4];
    const float* wth = (const float*)d_in[5];
    const float* bth = (const float*)d_in[6];
    const float* wph = (const float*)d_in[7];
    const float* bph = (const float*)d_in[8];
    const float* g2  = (const float*)d_in[9];
    const float* b2  = (const float*)d_in[10];
    const float* wz  = (const float*)d_in[11];
    const float* bz  = (const float*)d_in[12];
    float* out = (float*)d_out;

    static bool attr_set = false;
    if (!attr_set) {
        cudaFuncSetAttribute(k_final_mma, cudaFuncAttributeMaxDynamicSharedMemorySize, Z_SMEM);
        attr_set = true;
    }

    int prep_elems = OUTC * CC + CC * CG + OUTC + CG + BB * CI * CG;
    k_prep<<<(prep_elems + 255) / 256, 256>>>(wg, wth, wph, wz, bg, bth, bph);
    k_bn1<<<CC, 256>>>(x, g1, b1);
    {
        dim3 g(HW / 64, BB);
        k_fconv_mma<<<g, 256>>>(x);
    }
    {
        dim3 g(7, BB);
        k_M<<<g, 512>>>();
    }
    {
        dim3 g(HW / 64, BB);
        k_Y<<<g, 256>>>();
    }
    k_bn2<<<1, 64>>>(g2, b2);
    {
        dim3 g(HW / 64, BB);
        k_final_mma<<<g, 256, Z_SMEM>>>(x, bz, out);
    }
}

// round 9
// speedup vs baseline: 1.7073x; 1.0776x over previous
#include <cuda_runtime.h>
#include <cuda_bf16.h>
#include <cstdint>

#define BB 16
#define CC 256
#define HW 3136
#define CI 32
#define CG 64
#define NP 784
#define OUTC 128   /* theta(0..31) | g(32..95) | phi(96..127) */
#define EPSI 1e-5f
#define KAR_INV 0.03125f

// ---------------- scratch ----------------
__device__ __align__(128) float d_theta[(size_t)BB*CI*HW];
__device__ __align__(128) float d_hp[(size_t)BB*96*1568];   // h-pooled g/phi [b][ch][row*28+cp]
__device__ __align__(128) float d_M[BB*CI*CG];
__device__ __align__(128) __nv_bfloat16 d_yh[(size_t)BB*CG*HW];
__device__ __align__(128) __nv_bfloat16 d_yl[(size_t)BB*CG*HW];
__device__ __align__(128) __nv_bfloat16 d_Wch[OUTC*CC];   // hi  [128 o][256 k]
__device__ __align__(128) __nv_bfloat16 d_Wc2[OUTC*CC];   // karatsuba bf16(32w-31hi)
__device__ __align__(128) __nv_bfloat16 d_Wzh[CC*CG];     // [256 o][64 k] hi
__device__ __align__(128) __nv_bfloat16 d_Wzl[CC*CG];     // lo
__device__ float d_bc[OUTC];
__device__ float d_s1[CC], d_t1[CC];
__device__ float d_s2[CG], d_t2[CG];
__device__ float d_ysum[CG], d_ysumsq[CG];
__device__ float d_bsum[CC], d_bssq[CC];

// ---------------- helpers ----------------
#define SWZ128(off) ((off) ^ (((off) >> 3) & 0x70))

__device__ __forceinline__ uint32_t smem_u32(const void* p) {
    uint32_t a;
    asm("{ .reg .u64 t; cvta.to.shared.u64 t, %1; cvt.u32.u64 %0, t; }" : "=r"(a) : "l"(p));
    return a;
}
__device__ __forceinline__ void ldm_x4(uint32_t* r, uint32_t addr) {
    asm volatile("ldmatrix.sync.aligned.m8n8.x4.shared.b16 {%0,%1,%2,%3}, [%4];"
        : "=r"(r[0]),"=r"(r[1]),"=r"(r[2]),"=r"(r[3]) : "r"(addr));
}
__device__ __forceinline__ void ldm_x4_t(uint32_t* r, uint32_t addr) {
    asm volatile("ldmatrix.sync.aligned.m8n8.x4.trans.shared.b16 {%0,%1,%2,%3}, [%4];"
        : "=r"(r[0]),"=r"(r[1]),"=r"(r[2]),"=r"(r[3]) : "r"(addr));
}
__device__ __forceinline__ void mma16816(float* c, const uint32_t* a, const uint32_t* b) {
    asm volatile("mma.sync.aligned.m16n8k16.row.col.f32.bf16.bf16.f32 "
        "{%0,%1,%2,%3}, {%4,%5,%6,%7}, {%8,%9}, {%0,%1,%2,%3};"
        : "+f"(c[0]),"+f"(c[1]),"+f"(c[2]),"+f"(c[3])
        : "r"(a[0]),"r"(a[1]),"r"(a[2]),"r"(a[3]), "r"(b[0]),"r"(b[1]));
}
__device__ __forceinline__ uint32_t frag_addr(uint32_t base, int row0, int colb, int lane) {
    int g = lane >> 3, i = lane & 7;
    uint32_t off = (uint32_t)((row0 + i + (g & 1) * 8) * 128 + colb + (g >> 1) * 16);
    return base + SWZ128(off);
}
__device__ __forceinline__ uint32_t bf2u(__nv_bfloat162 v) {
    return *reinterpret_cast<uint32_t*>(&v);
}
__device__ __forceinline__ float2 u2f2(uint32_t u) {
    __nv_bfloat162 v = *reinterpret_cast<__nv_bfloat162*>(&u);
    return make_float2(__low2float(v), __high2float(v));
}
__device__ __forceinline__ void kar2(float f0, float f1, uint32_t& hi, uint32_t& k2) {
    __nv_bfloat162 h = __floats2bfloat162_rn(f0, f1);
    float h0 = __low2float(h), h1 = __high2float(h);
    __nv_bfloat162 s = __floats2bfloat162_rn(fmaf(32.f, f0, -31.f * h0),
                                             fmaf(32.f, f1, -31.f * h1));
    hi = bf2u(h); k2 = bf2u(s);
}
__device__ __forceinline__ float karc(float d1, float d2) { return fmaf(d2 - d1, KAR_INV, d1); }
__device__ __forceinline__ void hl2(float f0, float f1, uint32_t& hi, uint32_t& lo) {
    __nv_bfloat162 h = __floats2bfloat162_rn(f0, f1);
    __nv_bfloat162 l = __floats2bfloat162_rn(f0 - __low2float(h), f1 - __high2float(h));
    hi = bf2u(h); lo = bf2u(l);
}
__device__ __forceinline__ unsigned long long pk2(float lo, float hi) {
    unsigned long long r;
    asm("mov.b64 %0, {%1, %2};" : "=l"(r) : "f"(lo), "f"(hi));
    return r;
}
__device__ __forceinline__ void fma2(unsigned long long& d, unsigned long long a, unsigned long long b) {
    asm("fma.rn.f32x2 %0, %1, %2, %0;" : "+l"(d) : "l"(a), "l"(b));
}
__device__ __forceinline__ float2 upk2(unsigned long long v) {
    float lo, hi;
    asm("mov.b64 {%0, %1}, %2;" : "=f"(lo), "=f"(hi) : "l"(v));
    return make_float2(lo, hi);
}

// ---------------- K0: prep ----------------
__global__ void k_prep(const float* __restrict__ wg, const float* __restrict__ wth,
                       const float* __restrict__ wphi, const float* __restrict__ wz,
                       const float* __restrict__ bg, const float* __restrict__ bth,
                       const float* __restrict__ bphi) {
    int idx = blockIdx.x * 256 + threadIdx.x;
    if (idx < OUTC * CC) {
        int o = idx >> 8, k = idx & 255;
        float w;
        if (o < 32)      w = wth[o * CC + k];
        else if (o < 96) w = wg[(o - 32) * CC + k];
        else             w = wphi[(o - 96) * CC + k];
        __nv_bfloat16 h = __float2bfloat16(w);
        d_Wch[idx] = h;
        d_Wc2[idx] = __float2bfloat16(fmaf(32.f, w, -31.f * __bfloat162float(h)));
    }
    int j = idx - OUTC * CC;
    if (j >= 0 && j < CC * CG) {
        float w = wz[j];
        __nv_bfloat16 h = __float2bfloat16(w);
        d_Wzh[j] = h;
        d_Wzl[j] = __float2bfloat16(w - __bfloat162float(h));
    }
    int l = j - CC * CG;
    if (l >= 0 && l < OUTC)
        d_bc[l] = (l < 32) ? bth[l] : (l < 96 ? bg[l - 32] : bphi[l - 96]);
    if (l >= OUTC && l < OUTC + CG) {
        int c = l - OUTC;
        d_ysum[c] = 0.f; d_ysumsq[c] = 0.f;
    }
    int m = l - OUTC - CG;
    if (m >= 0 && m < BB * CI * CG) d_M[m] = 0.f;
    int s = m - BB * CI * CG;
    if (s >= 0 && s < CC) { d_bsum[s] = 0.f; d_bssq[s] = 0.f; }
}

// ---------------- K1: BN1 partial stats + finalize ----------------
__global__ void __launch_bounds__(256) k_bn1(const float* __restrict__ x) {
    int c = blockIdx.x;
    int bh = blockIdx.y;
    float s = 0.f, ss = 0.f;
    for (int b = bh * 8; b < bh * 8 + 8; b++) {
        const float4* p = (const float4*)(x + (size_t)(b * CC + c) * HW);
        for (int i = threadIdx.x; i < HW / 4; i += 256) {
            float4 v = p[i];
            s  += v.x + v.y + v.z + v.w;
            ss += v.x * v.x + v.y * v.y + v.z * v.z + v.w * v.w;
        }
    }
    for (int off = 16; off; off >>= 1) {
        s  += __shfl_down_sync(0xffffffffu, s, off);
        ss += __shfl_down_sync(0xffffffffu, ss, off);
    }
    __shared__ float rs[8], rss[8];
    int wid = threadIdx.x >> 5, lane = threadIdx.x & 31;
    if (lane == 0) { rs[wid] = s; rss[wid] = ss; }
    __syncthreads();
    if (threadIdx.x == 0) {
        float S = 0.f, SS = 0.f;
        for (int i = 0; i < 8; i++) { S += rs[i]; SS += rss[i]; }
        atomicAdd(&d_bsum[c], S);
        atomicAdd(&d_bssq[c], SS);
    }
}
__global__ void k_bn1fin(const float* __restrict__ g1, const float* __restrict__ b1) {
    int c = threadIdx.x;
    float n = (float)(BB * HW);
    float mean = d_bsum[c] / n;
    float var = d_bssq[c] / n - mean * mean;
    float rstd = rsqrtf(var + EPSI);
    float sc = g1[c] * rstd;
    d_s1[c] = sc;
    d_t1[c] = b1[c] - mean * sc;
}

// ---------------- K2: HMMA BN1+ReLU+conv1x1 karatsuba 2-pass, h-pool epilogue ----------------
__global__ void __launch_bounds__(256) k_fconv_mma(const float* __restrict__ x) {
    __shared__ __align__(128) char smem[49152];
    uint32_t sb = smem_u32(smem);
    const uint32_t sAH = sb, sA2 = sb + 16384, sBH = sb + 32768, sB2 = sb + 40960;
    int tid = threadIdx.x;
    int wid = tid >> 5, lane = tid & 31;
    int wm = wid >> 1, wn = wid & 1;
    int b = blockIdx.y;
    int p0 = blockIdx.x * 64;

    float a1[2][4][4], a2c[2][4][4];
#pragma unroll
    for (int mt = 0; mt < 2; mt++)
#pragma unroll
        for (int nf = 0; nf < 4; nf++)
#pragma unroll
            for (int q = 0; q < 4; q++) { a1[mt][nf][q] = 0.f; a2c[mt][nf][q] = 0.f; }

    for (int kc = 0; kc < 4; kc++) {
        int k0 = kc * 64;
        __syncthreads();
#pragma unroll
        for (int r = 0; r < 4; r++) {
            int idx = tid + r * 256;
            int row = idx >> 3, j = idx & 7;
            uint32_t sw = SWZ128((uint32_t)(row * 128 + j * 16));
            *(uint4*)(smem + sw)         = *(const uint4*)(d_Wch + row * CC + k0 + j * 8);
            *(uint4*)(smem + 16384 + sw) = *(const uint4*)(d_Wc2 + row * CC + k0 + j * 8);
        }
#pragma unroll
        for (int r = 0; r < 4; r++) {
            int idx = tid + r * 256;
            int ch = idx >> 4, pg = idx & 15;
            int c = k0 + ch;
            float4 v = *(const float4*)(x + (size_t)(b * CC + c) * HW + p0 + pg * 4);
            float sc = d_s1[c], sh = d_t1[c];
            float f0 = fmaxf(fmaf(v.x, sc, sh), 0.f);
            float f1 = fmaxf(fmaf(v.y, sc, sh), 0.f);
            float f2 = fmaxf(fmaf(v.z, sc, sh), 0.f);
            float f3 = fmaxf(fmaf(v.w, sc, sh), 0.f);
            uint32_t h01, k01, h23, k23;
            kar2(f0, f1, h01, k01);
            kar2(f2, f3, h23, k23);
            uint32_t sw = SWZ128((uint32_t)(ch * 128 + pg * 8));
            *(uint2*)(smem + 32768 + sw) = make_uint2(h01, h23);
            *(uint2*)(smem + 40960 + sw) = make_uint2(k01, k23);
        }
        __syncthreads();
#pragma unroll
        for (int ks = 0; ks < 4; ks++) {
            int k16 = ks * 16;
            uint32_t bh[2][4], b2[2][4];
            ldm_x4_t(bh[0], frag_addr(sBH, k16, wn * 64, lane));
            ldm_x4_t(bh[1], frag_addr(sBH, k16, wn * 64 + 32, lane));
            ldm_x4_t(b2[0], frag_addr(sB2, k16, wn * 64, lane));
            ldm_x4_t(b2[1], frag_addr(sB2, k16, wn * 64 + 32, lane));
#pragma unroll
            for (int mt = 0; mt < 2; mt++) {
                uint32_t ah[4], ak[4];
                ldm_x4(ah, frag_addr(sAH, wm * 32 + mt * 16, k16 * 2, lane));
                ldm_x4(ak, frag_addr(sA2, wm * 32 + mt * 16, k16 * 2, lane));
#pragma unroll
                for (int nf = 0; nf < 4; nf++) {
                    mma16816(a1[mt][nf], ah, &bh[nf >> 1][(nf & 1) * 2]);
                    mma16816(a2c[mt][nf], ak, &b2[nf >> 1][(nf & 1) * 2]);
                }
            }
        }
    }
    int g = lane >> 2, ti = lane & 3;
#pragma unroll
    for (int mt = 0; mt < 2; mt++) {
#pragma unroll
        for (int nf = 0; nf < 4; nf++) {
            int o = wm * 32 + mt * 16 + g;
            int pix = p0 + wn * 32 + nf * 8 + ti * 2;
            float b0 = d_bc[o], b8 = d_bc[o + 8];
            float v0 = karc(a1[mt][nf][0], a2c[mt][nf][0]) + b0;
            float v1 = karc(a1[mt][nf][1], a2c[mt][nf][1]) + b0;
            float v2 = karc(a1[mt][nf][2], a2c[mt][nf][2]) + b8;
            float v3 = karc(a1[mt][nf][3], a2c[mt][nf][3]) + b8;
            if (o < 32) {
                *(float2*)(d_theta + (size_t)(b * CI + o) * HW + pix) = make_float2(v0, v1);
                *(float2*)(d_theta + (size_t)(b * CI + o + 8) * HW + pix) = make_float2(v2, v3);
            } else {
                int row = pix / 56, cp = (pix % 56) >> 1;
                int hi = row * 28 + cp;
                d_hp[((size_t)b * 96 + (o - 32)) * 1568 + hi] = fmaxf(v0, v1);
                d_hp[((size_t)b * 96 + (o - 24)) * 1568 + hi] = fmaxf(v2, v3);
            }
        }
    }
}

// ---------------- K4: vertical pool + M[b] = phi @ g^T (2 pooled rows per block) ----------------
__global__ void __launch_bounds__(512) k_M() {
    int b = blockIdx.y;
    int pr0 = blockIdx.x * 2;          // pooled rows pr0, pr0+1 (56 positions)
    __shared__ float Ps[CI][57];
    __shared__ float Gs[CG][57];
    int tid = threadIdx.x;
    for (int u = tid; u < 96 * 56; u += 512) {
        int ch = u / 56, rem = u % 56;
        int prow = rem / 28, c = rem % 28;
        const float* src = d_hp + ((size_t)b * 96 + ch) * 1568 + (pr0 + prow) * 56 + c;
        float v = fmaxf(src[0], src[28]);
        if (ch < 64) Gs[ch][rem] = v;
        else         Ps[ch - 64][rem] = v;
    }
    __syncthreads();
#pragma unroll
    for (int q = 0; q < 4; q++) {
        int o = tid + q * 512;
        int i = o >> 6, c = o & 63;
        float acc = 0.f;
#pragma unroll 8
        for (int mm = 0; mm < 56; mm++) acc = fmaf(Ps[i][mm], Gs[c][mm], acc);
        atomicAdd(&d_M[(b * CI + i) * CG + c], acc);
    }
}

// ---------------- K5: y = (M/Np)^T @ theta + BN2 stats; y stored bf16 hi/lo ----------------
__global__ void __launch_bounds__(256) k_Y() {
    int b = blockIdx.y;
    int p0 = blockIdx.x * 64;
    __shared__ float Ms[CI * CG];
    __shared__ float Ts[CI * 64];
    __shared__ float bs[CG], bss[CG];
    int tid = threadIdx.x;
    const float invNp = 1.0f / (float)NP;
    for (int j = tid; j < CI * CG; j += 256) Ms[j] = d_M[b * CI * CG + j] * invNp;
    for (int j = tid; j < CI * 64; j += 256) {
        int i = j >> 6, col = j & 63;
        Ts[j] = d_theta[(size_t)(b * CI + i) * HW + p0 + col];
    }
    if (tid < CG) { bs[tid] = 0.f; bss[tid] = 0.f; }
    __syncthreads();
    int tx = tid & 15, ty = tid >> 4;
    unsigned long long acc[4][2];
#pragma unroll
    for (int ci = 0; ci < 4; ci++) { acc[ci][0] = 0ull; acc[ci][1] = 0ull; }
#pragma unroll 8
    for (int i = 0; i < CI; i++) {
        float4 mv = *(float4*)&Ms[i * CG + ty * 4];
        float4 tv = *(float4*)&Ts[i * 64 + tx * 4];
        unsigned long long t01 = pk2(tv.x, tv.y), t23 = pk2(tv.z, tv.w);
        float mm[4] = {mv.x, mv.y, mv.z, mv.w};
#pragma unroll
        for (int ci = 0; ci < 4; ci++) {
            unsigned long long md = pk2(mm[ci], mm[ci]);
            fma2(acc[ci][0], md, t01);
            fma2(acc[ci][1], md, t23);
        }
    }
#pragma unroll
    for (int ci = 0; ci < 4; ci++) {
        int cg = ty * 4 + ci;
        float2 a = upk2(acc[ci][0]), c2 = upk2(acc[ci][1]);
        uint32_t h01, l01, h23, l23;
        hl2(a.x, a.y, h01, l01);
        hl2(c2.x, c2.y, h23, l23);
        size_t yi = (size_t)(b * CG + cg) * HW + p0 + tx * 4;
        *(uint2*)(d_yh + yi) = make_uint2(h01, h23);
        *(uint2*)(d_yl + yi) = make_uint2(l01, l23);
        atomicAdd(&bs[cg], a.x + a.y + c2.x + c2.y);
        atomicAdd(&bss[cg], a.x * a.x + a.y * a.y + c2.x * c2.x + c2.y * c2.y);
    }
    __syncthreads();
    if (tid < CG) {
        atomicAdd(&d_ysum[tid], bs[tid]);
        atomicAdd(&d_ysumsq[tid], bss[tid]);
    }
}

// ---------------- K5b: BN2 scale/shift ----------------
__global__ void k_bn2(const float* __restrict__ g2, const float* __restrict__ b2) {
    int c = threadIdx.x;
    if (c < CG) {
        float n = (float)(BB * HW);
        float mean = d_ysum[c] / n;
        float var = d_ysumsq[c] / n - mean * mean;
        float rstd = rsqrtf(var + EPSI);
        float sc = g2[c] * rstd;
        d_s2[c] = sc;
        d_t2[c] = b2[c] - mean * sc;
    }
}

// ---------------- K6: HMMA BN2+ReLU+conv(64->256)+bias+identity (3-pass) ----------------
#define Z_SMEM 81920
__global__ void __launch_bounds__(256) k_final_mma(const float* __restrict__ x,
                                                   const float* __restrict__ bz,
                                                   float* __restrict__ out) {
    extern __shared__ __align__(128) char smem[];
    uint32_t sb = smem_u32(smem);
    const uint32_t sAH = sb, sAL = sb + 32768, sBH = sb + 65536, sBL = sb + 73728;
    int tid = threadIdx.x;
    int wid = tid >> 5, lane = tid & 31;
    int wm = wid >> 1, wn = wid & 1;
    int b = blockIdx.y;
    int p0 = blockIdx.x * 64;

#pragma unroll
    for (int r = 0; r < 8; r++) {
        int idx = tid + r * 256;
        int row = idx >> 3, j = idx & 7;
        uint32_t sw = SWZ128((uint32_t)(row * 128 + j * 16));
        *(uint4*)(smem + sw)         = *(const uint4*)(d_Wzh + row * CG + j * 8);
        *(uint4*)(smem + 32768 + sw) = *(const uint4*)(d_Wzl + row * CG + j * 8);
    }
#pragma unroll
    for (int r = 0; r < 4; r++) {
        int idx = tid + r * 256;
        int ch = idx >> 4, pg = idx & 15;
        size_t yi = (size_t)(b * CG + ch) * HW + p0 + pg * 4;
        uint2 hv = *(const uint2*)(d_yh + yi);
        uint2 lv = *(const uint2*)(d_yl + yi);
        float2 h0 = u2f2(hv.x), h1 = u2f2(hv.y);
        float2 l0 = u2f2(lv.x), l1 = u2f2(lv.y);
        float sc = d_s2[ch], sh = d_t2[ch];
        float f0 = fmaxf(fmaf(h0.x + l0.x, sc, sh), 0.f);
        float f1 = fmaxf(fmaf(h0.y + l0.y, sc, sh), 0.f);
        float f2 = fmaxf(fmaf(h1.x + l1.x, sc, sh), 0.f);
        float f3 = fmaxf(fmaf(h1.y + l1.y, sc, sh), 0.f);
        uint32_t h01, l01, h23, l23;
        hl2(f0, f1, h01, l01);
        hl2(f2, f3, h23, l23);
        uint32_t sw = SWZ128((uint32_t)(ch * 128 + pg * 8));
        *(uint2*)(smem + 65536 + sw) = make_uint2(h01, h23);
        *(uint2*)(smem + 73728 + sw) = make_uint2(l01, l23);
    }
    __syncthreads();

    float acc[4][4][4];
#pragma unroll
    for (int mt = 0; mt < 4; mt++)
#pragma unroll
        for (int nf = 0; nf < 4; nf++)
#pragma unroll
            for (int q = 0; q < 4; q++) acc[mt][nf][q] = 0.f;

#pragma unroll
    for (int ks = 0; ks < 4; ks++) {
        int k16 = ks * 16;
        uint32_t bh[2][4], bl[2][4];
        ldm_x4_t(bh[0], frag_addr(sBH, k16, wn * 64, lane));
        ldm_x4_t(bh[1], frag_addr(sBH, k16, wn * 64 + 32, lane));
        ldm_x4_t(bl[0], frag_addr(sBL, k16, wn * 64, lane));
        ldm_x4_t(bl[1], frag_addr(sBL, k16, wn * 64 + 32, lane));
#pragma unroll
        for (int mt = 0; mt < 4; mt++) {
            uint32_t ah[4], al[4];
            ldm_x4(ah, frag_addr(sAH, wm * 64 + mt * 16, k16 * 2, lane));
            ldm_x4(al, frag_addr(sAL, wm * 64 + mt * 16, k16 * 2, lane));
#pragma unroll
            for (int nf = 0; nf < 4; nf++) {
                const uint32_t* bhf = &bh[nf >> 1][(nf & 1) * 2];
                const uint32_t* blf = &bl[nf >> 1][(nf & 1) * 2];
                mma16816(acc[mt][nf], ah, bhf);
                mma16816(acc[mt][nf], ah, blf);
                mma16816(acc[mt][nf], al, bhf);
            }
        }
    }
    int g = lane >> 2, ti = lane & 3;
#pragma unroll
    for (int mt = 0; mt < 4; mt++) {
#pragma unroll
        for (int nf = 0; nf < 4; nf++) {
            int o = wm * 64 + mt * 16 + g;
            int pix = p0 + wn * 32 + nf * 8 + ti * 2;
            float b0 = __ldg(&bz[o]), b8 = __ldg(&bz[o + 8]);
            size_t off0 = (size_t)(b * CC + o) * HW + pix;
            size_t off1 = (size_t)(b * CC + o + 8) * HW + pix;
            float2 i0 = *(const float2*)(x + off0);
            float2 i1 = *(const float2*)(x + off1);
            *(float2*)(out + off0) = make_float2(acc[mt][nf][0] + b0 + i0.x,
                                                 acc[mt][nf][1] + b0 + i0.y);
            *(float2*)(out + off1) = make_float2(acc[mt][nf][2] + b8 + i1.x,
                                                 acc[mt][nf][3] + b8 + i1.y);
        }
    }
}

// ---------------- host ----------------
extern "C" void kernel_launch(void* const* d_in, const int* in_sizes, int n_in,
                              void* d_out, int out_size) {
    const float* x   = (const float*)d_in[0];
    const float* g1  = (const float*)d_in[1];
    const float* b1  = (const float*)d_in[2];
    const float* wg  = (const float*)d_in[3];
    const float* bg  = (const float*)d_in[4];
    const float* wth = (const float*)d_in[5];
    const float* bth = (const float*)d_in[6];
    const float* wph = (const float*)d_in[7];
    const float* bph = (const float*)d_in[8];
    const float* g2  = (const float*)d_in[9];
    const float* b2  = (const float*)d_in[10];
    const float* wz  = (const float*)d_in[11];
    const float* bz  = (const float*)d_in[12];
    float* out = (float*)d_out;

    static bool attr_set = false;
    if (!attr_set) {
        cudaFuncSetAttribute(k_final_mma, cudaFuncAttributeMaxDynamicSharedMemorySize, Z_SMEM);
        attr_set = true;
    }

    int prep_elems = OUTC * CC + CC * CG + OUTC + CG + BB * CI * CG + CC;
    k_prep<<<(prep_elems + 255) / 256, 256>>>(wg, wth, wph, wz, bg, bth, bph);
    {
        dim3 g(CC, 2);
        k_bn1<<<g, 256>>>(x);
    }
    k_bn1fin<<<1, CC>>>(g1, b1);
    {
        dim3 g(HW / 64, BB);
        k_fconv_mma<<<g, 256>>>(x);
    }
    {
        dim3 g(14, BB);
        k_M<<<g, 512>>>();
    }
    {
        dim3 g(HW / 64, BB);
        k_Y<<<g, 256>>>();
    }
    k_bn2<<<1, 64>>>(g2, b2);
    {
        dim3 g(HW / 64, BB);
        k_final_mma<<<g, 256, Z_SMEM>>>(x, bz, out);
    }
}